// round 1
// baseline (speedup 1.0000x reference)
#include <cuda_runtime.h>
#include <cuda_bf16.h>

#define NN 20000
#define EE 320000
#define TE (EE + NN)          // edges + self loops
#define FIN 128
#define HID 64
#define HEADS 8
#define C1 (HEADS * HID)      // 512

// ---------------- scratch (static device globals; no allocation) -------------
__device__ int   g_is64;
__device__ int   g_cnt[NN];
__device__ int   g_off[NN + 1];
__device__ int   g_cur[NN];
__device__ int   g_csr[TE];
__device__ float g_h1[(size_t)NN * C1];   // 41 MB
__device__ float g_as1[NN * HEADS];
__device__ float g_ad1[NN * HEADS];
__device__ float g_h2[NN * 2];
__device__ float g_as2[NN];
__device__ float g_ad2[NN];

// ---------------- dtype detection for edge_index -----------------------------
__global__ void k_detect(const int* ei) {
    int lane = threadIdx.x;
    int hi = ei[2 * lane + 1];
    unsigned b = __ballot_sync(0xffffffffu, hi == 0);
    if (lane == 0) g_is64 = (b == 0xffffffffu) ? 1 : 0;
}

__device__ __forceinline__ void load_edge(const void* ei, int e, int& src, int& dst) {
    if (e < EE) {
        if (g_is64) {
            const long long* p = (const long long*)ei;
            src = (int)p[e];
            dst = (int)p[EE + e];
        } else {
            const int* p = (const int*)ei;
            src = p[e];
            dst = p[EE + e];
        }
    } else {
        src = dst = e - EE;   // self loop
    }
}

// ---------------- CSR build ---------------------------------------------------
__global__ void k_zero() {
    int i = blockIdx.x * blockDim.x + threadIdx.x;
    if (i < NN) g_cnt[i] = 0;
}

__global__ void k_count(const void* ei) {
    int e = blockIdx.x * blockDim.x + threadIdx.x;
    if (e >= TE) return;
    int s, d;
    load_edge(ei, e, s, d);
    atomicAdd(&g_cnt[d], 1);
}

__global__ void k_scan() {   // <<<1,1024>>>
    __shared__ int sm[1024];
    int t = threadIdx.x;
    int carry = 0;
    if (t == 0) g_off[0] = 0;
    for (int base = 0; base < NN; base += 1024) {
        int i = base + t;
        int v = (i < NN) ? g_cnt[i] : 0;
        sm[t] = v;
        __syncthreads();
        for (int d = 1; d < 1024; d <<= 1) {
            int x = (t >= d) ? sm[t - d] : 0;
            __syncthreads();
            sm[t] += x;
            __syncthreads();
        }
        int incl = sm[t];
        if (i < NN) {
            g_off[i + 1] = carry + incl;
            g_cur[i] = carry + incl - v;
        }
        int tot = sm[1023];
        __syncthreads();
        carry += tot;
    }
}

__global__ void k_scatter(const void* ei) {
    int e = blockIdx.x * blockDim.x + threadIdx.x;
    if (e >= TE) return;
    int s, d;
    load_edge(ei, e, s, d);
    int pos = atomicAdd(&g_cur[d], 1);
    g_csr[pos] = s;
}

// ---------------- GEMM1: h1 = x @ W1, fused a_src1/a_dst1 epilogue -----------
// grid (313, 8) ; block 256 ; BM=64, BN=64 (one head per blockIdx.y), BK=64x2
__global__ void k_gemm1(const float* __restrict__ x, const float* __restrict__ W1,
                        const float* __restrict__ att_s, const float* __restrict__ att_d) {
    __shared__ __align__(16) float sA[64][68];   // transposed A: sA[k][m]
    __shared__ __align__(16) float sB[64][64];   // sB[k][n]
    int tid = threadIdx.x;
    int row0 = blockIdx.x * 64;
    int head = blockIdx.y;
    int col0 = head * 64;
    int tx = tid & 15, ty = tid >> 4;

    float c[4][4] = {};

    for (int kk = 0; kk < 128; kk += 64) {
        // load A tile (transposed into smem)
        #pragma unroll
        for (int r = 0; r < 4; r++) {
            int idx = tid + 256 * r;       // 0..1023
            int m = idx >> 4;              // 0..63
            int kq = idx & 15;             // float4 index in 64 k's
            int grow = row0 + m;
            float4 v = make_float4(0.f, 0.f, 0.f, 0.f);
            if (grow < NN) v = *(const float4*)&x[(size_t)grow * FIN + kk + kq * 4];
            sA[kq * 4 + 0][m] = v.x;
            sA[kq * 4 + 1][m] = v.y;
            sA[kq * 4 + 2][m] = v.z;
            sA[kq * 4 + 3][m] = v.w;
        }
        // load B tile
        #pragma unroll
        for (int r = 0; r < 4; r++) {
            int idx = tid + 256 * r;
            int k = idx >> 4;
            int cq = idx & 15;
            *(float4*)&sB[k][cq * 4] = *(const float4*)&W1[(size_t)(kk + k) * C1 + col0 + cq * 4];
        }
        __syncthreads();
        #pragma unroll 16
        for (int k = 0; k < 64; k++) {
            float4 a = *(float4*)&sA[k][ty * 4];
            float4 b = *(float4*)&sB[k][tx * 4];
            c[0][0] += a.x * b.x; c[0][1] += a.x * b.y; c[0][2] += a.x * b.z; c[0][3] += a.x * b.w;
            c[1][0] += a.y * b.x; c[1][1] += a.y * b.y; c[1][2] += a.y * b.z; c[1][3] += a.y * b.w;
            c[2][0] += a.z * b.x; c[2][1] += a.z * b.y; c[2][2] += a.z * b.z; c[2][3] += a.z * b.w;
            c[3][0] += a.w * b.x; c[3][1] += a.w * b.y; c[3][2] += a.w * b.z; c[3][3] += a.w * b.w;
        }
        __syncthreads();
    }

    // attention vectors for this head, this thread's 4 channels
    float as_[4], ad_[4];
    #pragma unroll
    for (int j = 0; j < 4; j++) {
        as_[j] = att_s[head * HID + tx * 4 + j];
        ad_[j] = att_d[head * HID + tx * 4 + j];
    }

    #pragma unroll
    for (int i = 0; i < 4; i++) {
        float ps = 0.f, pd = 0.f;
        #pragma unroll
        for (int j = 0; j < 4; j++) {
            ps += c[i][j] * as_[j];
            pd += c[i][j] * ad_[j];
        }
        #pragma unroll
        for (int off = 8; off >= 1; off >>= 1) {
            ps += __shfl_xor_sync(0xffffffffu, ps, off);
            pd += __shfl_xor_sync(0xffffffffu, pd, off);
        }
        int grow = row0 + ty * 4 + i;
        if (grow < NN) {
            *(float4*)&g_h1[(size_t)grow * C1 + head * HID + tx * 4] =
                make_float4(c[i][0], c[i][1], c[i][2], c[i][3]);
            if (tx == 0) {
                g_as1[grow * HEADS + head] = ps;
                g_ad1[grow * HEADS + head] = pd;
            }
        }
    }
}

// ---------------- layer-1 aggregation + fused layer-2 GEMM per node ----------
// one warp per dst node; 2500 blocks x 256 threads
__global__ void k_agg1(const float* __restrict__ b1, const float* __restrict__ W2,
                       const float* __restrict__ att_s2, const float* __restrict__ att_d2) {
    __shared__ float sW2[C1 * 2];
    __shared__ float sb1[C1];
    int tid = threadIdx.x;
    for (int j = tid; j < C1 * 2; j += 256) sW2[j] = W2[j];
    for (int j = tid; j < C1; j += 256) sb1[j] = b1[j];
    __syncthreads();

    int node = (blockIdx.x * 256 + tid) >> 5;
    if (node >= NN) return;
    int lane = tid & 31;
    int head = lane >> 2;     // 4 lanes per head for the accumulator slice

    int beg = g_off[node], end = g_off[node + 1];
    float adst = (lane < 8) ? g_ad1[node * HEADS + lane] : 0.f;

    float m = -1e30f, s = 0.f;
    float acc[16];
    #pragma unroll
    for (int j = 0; j < 16; j++) acc[j] = 0.f;

    for (int e = beg; e < end; e++) {
        int src = g_csr[e];
        float w_h = 0.f, sc_h = 0.f;
        if (lane < 8) {
            float al = g_as1[src * HEADS + lane] + adst;
            al = al > 0.f ? al : 0.2f * al;
            if (al <= m) {
                w_h = __expf(al - m);
                sc_h = 1.f;
                s += w_h;
            } else {
                sc_h = __expf(m - al);   // 0 on first edge (m=-1e30)
                w_h = 1.f;
                s = s * sc_h + 1.f;
                m = al;
            }
        }
        float w  = __shfl_sync(0xffffffffu, w_h, head);
        float sc = __shfl_sync(0xffffffffu, sc_h, head);
        const float4* hp = (const float4*)&g_h1[(size_t)src * C1 + lane * 16];
        #pragma unroll
        for (int q = 0; q < 4; q++) {
            float4 h = hp[q];
            acc[4 * q + 0] = acc[4 * q + 0] * sc + w * h.x;
            acc[4 * q + 1] = acc[4 * q + 1] * sc + w * h.y;
            acc[4 * q + 2] = acc[4 * q + 2] * sc + w * h.z;
            acc[4 * q + 3] = acc[4 * q + 3] * sc + w * h.w;
        }
    }

    float inv_h = (lane < 8) ? (1.f / s) : 0.f;
    float inv = __shfl_sync(0xffffffffu, inv_h, head);

    // out1 = acc/s + b1 ; elu ; h2 = elu(out1) @ W2 (no bias yet)
    float p0 = 0.f, p1 = 0.f;
    #pragma unroll
    for (int j = 0; j < 16; j++) {
        int ch = lane * 16 + j;
        float o = acc[j] * inv + sb1[ch];
        float he = o > 0.f ? o : expm1f(o);
        p0 += he * sW2[ch * 2 + 0];
        p1 += he * sW2[ch * 2 + 1];
    }
    #pragma unroll
    for (int off = 16; off >= 1; off >>= 1) {
        p0 += __shfl_xor_sync(0xffffffffu, p0, off);
        p1 += __shfl_xor_sync(0xffffffffu, p1, off);
    }
    if (lane == 0) {
        g_h2[node * 2 + 0] = p0;
        g_h2[node * 2 + 1] = p1;
        g_as2[node] = p0 * att_s2[0] + p1 * att_s2[1];
        g_ad2[node] = p0 * att_d2[0] + p1 * att_d2[1];
    }
}

// ---------------- layer-2 aggregation ----------------------------------------
// one warp per dst node, lane-parallel over edges with online-softmax merge
__global__ void k_agg2(const float* __restrict__ b2, float* __restrict__ out) {
    int tid = threadIdx.x;
    int node = (blockIdx.x * 256 + tid) >> 5;
    if (node >= NN) return;
    int lane = tid & 31;

    int beg = g_off[node], end = g_off[node + 1];
    float adst = g_ad2[node];

    float m = -1e30f, s = 0.f, a0 = 0.f, a1 = 0.f;
    for (int e = beg + lane; e < end; e += 32) {
        int src = g_csr[e];
        float al = g_as2[src] + adst;
        al = al > 0.f ? al : 0.2f * al;
        float h0 = g_h2[src * 2 + 0];
        float h1v = g_h2[src * 2 + 1];
        if (al <= m) {
            float w = __expf(al - m);
            s += w;
            a0 += w * h0;
            a1 += w * h1v;
        } else {
            float sc = __expf(m - al);
            m = al;
            s = s * sc + 1.f;
            a0 = a0 * sc + h0;
            a1 = a1 * sc + h1v;
        }
    }
    // warp tree merge of (m, s, a0, a1)
    #pragma unroll
    for (int off = 16; off >= 1; off >>= 1) {
        float m2 = __shfl_xor_sync(0xffffffffu, m, off);
        float s2 = __shfl_xor_sync(0xffffffffu, s, off);
        float b0 = __shfl_xor_sync(0xffffffffu, a0, off);
        float b1v = __shfl_xor_sync(0xffffffffu, a1, off);
        float M = fmaxf(m, m2);
        float e1 = __expf(m - M);
        float e2 = __expf(m2 - M);
        s = s * e1 + s2 * e2;
        a0 = a0 * e1 + b0 * e2;
        a1 = a1 * e1 + b1v * e2;
        m = M;
    }
    if (lane == 0) {
        float inv = 1.f / s;
        out[node * 2 + 0] = a0 * inv + b2[0];
        out[node * 2 + 1] = a1 * inv + b2[1];
    }
}

// ---------------- launch ------------------------------------------------------
extern "C" void kernel_launch(void* const* d_in, const int* in_sizes, int n_in,
                              void* d_out, int out_size) {
    const float* x   = (const float*)d_in[0];
    const void*  ei  = d_in[1];
    const float* W1  = (const float*)d_in[2];
    const float* as1 = (const float*)d_in[3];
    const float* ad1 = (const float*)d_in[4];
    const float* b1  = (const float*)d_in[5];
    const float* W2  = (const float*)d_in[6];
    const float* as2 = (const float*)d_in[7];
    const float* ad2 = (const float*)d_in[8];
    const float* b2  = (const float*)d_in[9];
    float* out = (float*)d_out;

    k_detect<<<1, 32>>>((const int*)ei);
    k_zero<<<(NN + 255) / 256, 256>>>();
    k_count<<<(TE + 255) / 256, 256>>>(ei);
    k_scan<<<1, 1024>>>();
    k_scatter<<<(TE + 255) / 256, 256>>>(ei);
    k_gemm1<<<dim3((NN + 63) / 64, HEADS), 256>>>(x, W1, as1, ad1);
    k_agg1<<<(NN * 32 + 255) / 256, 256>>>(b1, W2, as2, ad2);
    k_agg2<<<(NN * 32 + 255) / 256, 256>>>(b2, out);
}